// round 9
// baseline (speedup 1.0000x reference)
#include <cuda_runtime.h>
#include <math.h>

#define BB 32
#define NN 1024
#define FF 64
#define HH 24
#define L2E 1.4426950408889634f

// Scratch (allocation-free: __device__ globals)
__device__ float g_Z[BB * NN * HH];       // relu(linear) activations, 3 MB
__device__ float g_G[BB * 36 * 16384];    // lower-tri tiles of g=exp2(aL-C), K2-thread-order, 75.5 MB
__device__ float g_s[BB * NN];            // S_n = sum_m g (atomic accum)
__device__ float g_c[BB * NN];            // c_n = sum_m P_mn (atomic accum)
__device__ int   g_M[BB];                 // per-batch max row norm (bits; atomicMax replay-idempotent)

static __device__ __forceinline__ float ex2f_(float x) {
    float r; asm("ex2.approx.ftz.f32 %0, %1;" : "=f"(r) : "f"(x)); return r;
}
static __device__ __forceinline__ float rsq_(float x) {
    float r; asm("rsqrt.approx.f32 %0, %1;" : "=f"(r) : "f"(x)); return r;
}

// Butterfly transpose-reduce: 32 per-thread slot partials -> lane l holds the
// 32-lane sum of slot l (identity slot mapping; verified rounds 5-7).
static __device__ __forceinline__ float butterfly32_(float* c, int lane) {
    #pragma unroll
    for (int m = 16; m >= 1; m >>= 1) {
        const bool hi = (lane & m) != 0;
        #pragma unroll
        for (int i = 0; i < m; i++) {
            float sent = hi ? c[i] : c[i + m];
            float recv = __shfl_xor_sync(0xffffffffu, sent, m);
            c[i] = (hi ? c[i + m] : c[i]) + recv;
        }
    }
    return c[0];
}

// ---------------------------------------------------------------------------
// K1: Z = relu(xt @ W + b), batch max norm M_b; also zeroes g_s/g_c.
// ---------------------------------------------------------------------------
__global__ void __launch_bounds__(256) k1_linrelu(
    const float* __restrict__ xt, const float* __restrict__ W,
    const float* __restrict__ bias)
{
    __shared__ float xs[64][65];
    __shared__ float Ws[FF][HH];
    __shared__ float bs[HH];
    const int tid = threadIdx.x;
    const int base = blockIdx.x * 64;

    if (tid < 64) {                       // 512 blocks x 64 = 32768: zero accumulators
        g_s[base + tid] = 0.f;
        g_c[base + tid] = 0.f;
    }

    const float4* xt4 = (const float4*)(xt + (size_t)base * FF);
    for (int i = tid; i < 1024; i += 256) {
        float4 v = xt4[i];
        int row = i >> 4, c = (i & 15) << 2;
        xs[row][c] = v.x; xs[row][c + 1] = v.y; xs[row][c + 2] = v.z; xs[row][c + 3] = v.w;
    }
    for (int i = tid; i < FF * HH; i += 256) Ws[i / HH][i % HH] = W[i];
    if (tid < HH) bs[tid] = bias[tid];
    __syncthreads();

    const int row = tid >> 2, hg = tid & 3, h0 = hg * 6;
    float acc[6];
    #pragma unroll
    for (int j = 0; j < 6; j++) acc[j] = bs[h0 + j];
    #pragma unroll 8
    for (int k = 0; k < FF; k++) {
        float xa = xs[row][k];
        #pragma unroll
        for (int j = 0; j < 6; j++) acc[j] = fmaf(xa, Ws[k][h0 + j], acc[j]);
    }
    const int g = base + row;
    float ss = 0.f;
    #pragma unroll
    for (int j = 0; j < 6; j++) {
        float z = fmaxf(acc[j], 0.f);
        g_Z[(size_t)g * HH + h0 + j] = z;
        ss = fmaf(z, z, ss);
    }
    ss += __shfl_xor_sync(0xffffffffu, ss, 1);
    ss += __shfl_xor_sync(0xffffffffu, ss, 2);
    if (hg == 0) {
        float rn = sqrtf(ss);
        atomicMax(&g_M[base >> 10], __float_as_int(rn));  // rn>=0: int order == float order
    }
}

// ---------------------------------------------------------------------------
// Common triangular tile indices. grid = BB*36; t -> (ti, tj), ti >= tj.
// ---------------------------------------------------------------------------
#define TILE_COMMON() \
    const int tid = threadIdx.x, w = tid >> 5, lane = tid & 31;      \
    const int b = blockIdx.x / 36, t = blockIdx.x % 36;              \
    int ti = (int)((sqrtf(8.f * t + 1.f) - 1.f) * 0.5f);             \
    while ((ti + 1) * (ti + 2) / 2 <= t) ti++;                       \
    while (ti * (ti + 1) / 2 > t) ti--;                              \
    const int tj = t - ti * (ti + 1) / 2;                            \
    const int colbase = b * NN + tj * 128;                           \
    float* gtile = g_G + ((size_t)blockIdx.x << 14);                 \
    const bool offd = (ti != tj);

// K2 (producer) warp decomposition: 8 warps = rhalf(2) x wc(4)
#define TILE_IDX() \
    TILE_COMMON();                                                   \
    const int rhalf = w >> 2, wc = w & 3;                            \
    const int nloc = rhalf * 64 + lane * 2;                          \
    const int growR = b * NN + ti * 128 + nloc;

// Consumer (K3/K5) warp decomposition: 8 warps = rhalf(2) x wc2(2) x jw(2).
// Thread owns rows nloc,nloc+1 and, per jj, 8 consecutive cols
// cb = (jw*4+jj)*16 + wc2*8 -- two adjacent K2 chunks.
#define TILE_IDX2() \
    TILE_COMMON();                                                   \
    const int rhalf = w >> 2, wc2 = w & 1, jw = (w >> 1) & 1;        \
    const int nloc = rhalf * 64 + lane * 2;                          \
    const int growR = b * NN + ti * 128 + nloc;

#define TILE_ZR() \
    float zr[2][24];                                                 \
    {                                                                \
        const float4* zg = (const float4*)g_Z;                       \
        _Pragma("unroll")                                            \
        for (int r = 0; r < 2; r++) {                                \
            _Pragma("unroll")                                        \
            for (int kk = 0; kk < 6; kk++) {                         \
                float4 v = zg[(size_t)(growR + r) * 6 + kk];         \
                zr[r][kk * 4 + 0] = v.x; zr[r][kk * 4 + 1] = v.y;    \
                zr[r][kk * 4 + 2] = v.z; zr[r][kk * 4 + 3] = v.w;    \
            }                                                        \
        }                                                            \
    }

#define GRAM_DOT(cb)                                                 \
    float a[2][4] = {};                                              \
    {                                                                \
        _Pragma("unroll")                                            \
        for (int kk = 0; kk < 6; kk++) {                             \
            float4 bq[4];                                            \
            _Pragma("unroll")                                        \
            for (int q = 0; q < 4; q++) bq[q] = Zc4[((cb) + q) * 6 + kk]; \
            _Pragma("unroll")                                        \
            for (int r = 0; r < 2; r++) {                            \
                _Pragma("unroll")                                    \
                for (int q = 0; q < 4; q++) {                        \
                    a[r][q] = fmaf(zr[r][kk * 4 + 0], bq[q].x, a[r][q]); \
                    a[r][q] = fmaf(zr[r][kk * 4 + 1], bq[q].y, a[r][q]); \
                    a[r][q] = fmaf(zr[r][kk * 4 + 2], bq[q].z, a[r][q]); \
                    a[r][q] = fmaf(zr[r][kk * 4 + 3], bq[q].w, a[r][q]); \
                }                                                    \
            }                                                        \
        }                                                            \
    }

// Consumer half-hoist: 8 float4s covering jj = s*2, s*2+1 (rows n0,n0+1;
// 8 cols per jj from two adjacent K2 chunks).
#define LOAD_G_HALF(s)                                               \
    float4 G[2][4];                                                  \
    {                                                                \
        const float4* gp = (const float4*)gtile;                     \
        _Pragma("unroll")                                            \
        for (int jj = 0; jj < 2; jj++) {                             \
            const int j = jw * 4 + (s) * 2 + jj;                     \
            const int b4 = (j * 256 + (rhalf * 4 + wc2 * 2) * 32 + lane) * 2; \
            G[jj][0] = gp[b4];      G[jj][1] = gp[b4 + 1];           \
            G[jj][2] = gp[b4 + 64]; G[jj][3] = gp[b4 + 65];          \
        }                                                            \
    }

#define UNPACK_G(jj)                                                 \
    float a0[8], a1[8];                                              \
    a0[0] = G[jj][0].x; a0[1] = G[jj][0].y; a0[2] = G[jj][0].z; a0[3] = G[jj][0].w; \
    a0[4] = G[jj][2].x; a0[5] = G[jj][2].y; a0[6] = G[jj][2].z; a0[7] = G[jj][2].w; \
    a1[0] = G[jj][1].x; a1[1] = G[jj][1].y; a1[2] = G[jj][1].z; a1[3] = G[jj][1].w; \
    a1[4] = G[jj][3].x; a1[5] = G[jj][3].y; a1[6] = G[jj][3].z; a1[7] = G[jj][3].w;

// ---------------------------------------------------------------------------
// K2: the only gram pass. a = <Z_n,Z_m>; g = exp2(a*L2E - C), C = M_b^2*L2E
// (g <= 1, S <= 1024: overflow-free). Stores g; accumulates S_n row-side
// (regs) and, off-diag, col-side via register partials + butterfly.
// ---------------------------------------------------------------------------
__global__ void __launch_bounds__(256) k2_gram() {
    __shared__ float Zc[128 * 24];
    __shared__ float sred[4][128];
    __shared__ float scol[2][128];
    float4* Zc4 = (float4*)Zc;
    TILE_IDX();
    TILE_ZR();
    const float M = __int_as_float(g_M[b]);
    const float C = M * M * L2E;
    {
        const float4* src = (const float4*)(g_Z + (size_t)colbase * HH);
        for (int i = tid; i < 768; i += 256) Zc4[i] = src[i];
    }
    float s0 = 0.f, s1 = 0.f;
    float ccol[32];
    #pragma unroll
    for (int i = 0; i < 32; i++) ccol[i] = 0.f;
    __syncthreads();

    #pragma unroll 2
    for (int j = 0; j < 8; j++) {
        const int cb = wc * 4 + j * 16;
        GRAM_DOT(cb);
        float g0[4], g1[4];
        #pragma unroll
        for (int q = 0; q < 4; q++) {
            g0[q] = ex2f_(fmaf(a[0][q], L2E, -C));
            g1[q] = ex2f_(fmaf(a[1][q], L2E, -C));
        }
        float4* gp = (float4*)(gtile + ((j * 256 + tid) << 3));
        gp[0] = make_float4(g0[0], g0[1], g0[2], g0[3]);
        gp[1] = make_float4(g1[0], g1[1], g1[2], g1[3]);
        #pragma unroll
        for (int q = 0; q < 4; q++) {
            s0 += g0[q];
            s1 += g1[q];
            ccol[j * 4 + q] += g0[q] + g1[q];
        }
    }
    sred[wc][nloc] = s0;
    sred[wc][nloc + 1] = s1;
    if (offd) {
        float cs = butterfly32_(ccol, lane);   // lane l holds slot l = j*4+q
        scol[rhalf][wc * 4 + (lane & 3) + 16 * (lane >> 2)] = cs;
    }
    __syncthreads();
    if (tid < 128) {
        float s = sred[0][tid] + sred[1][tid] + sred[2][tid] + sred[3][tid];
        atomicAdd(&g_s[b * NN + ti * 128 + tid], s);
        if (offd) atomicAdd(&g_s[colbase + tid], scol[0][tid] + scol[1][tid]);
    }
}

// ---------------------------------------------------------------------------
// K3: column sums of P from stored g. P_nm = g*w_n, w = 1/S.
// Two half-phases of hoisted loads (fewer regs in flight than round 7).
// ---------------------------------------------------------------------------
__global__ void __launch_bounds__(256) k3_colsum() {
    __shared__ float wv[128];
    __shared__ float cred[4][128];
    __shared__ float scol[2][128];
    TILE_IDX2();
    if (tid < 128) wv[tid] = 1.0f / g_s[colbase + tid];
    const float w0 = 1.0f / g_s[growR];
    const float w1 = 1.0f / g_s[growR + 1];
    float c0 = 0.f, c1 = 0.f;
    float ccol[32];
    #pragma unroll
    for (int i = 0; i < 32; i++) ccol[i] = 0.f;
    __syncthreads();

    #pragma unroll
    for (int s = 0; s < 2; s++) {
        LOAD_G_HALF(s);
        #pragma unroll
        for (int jj = 0; jj < 2; jj++) {
            const int jg = s * 2 + jj;
            const int cb = (jw * 4 + jg) * 16 + wc2 * 8;
            UNPACK_G(jj);
            #pragma unroll
            for (int q = 0; q < 8; q++) {
                float wm = wv[cb + q];
                c0 = fmaf(a0[q], wm, c0);
                c1 = fmaf(a1[q], wm, c1);
                ccol[jg * 8 + q] += fmaf(a0[q], w0, a1[q] * w1);
            }
        }
    }
    cred[w & 3][nloc] = c0;
    cred[w & 3][nloc + 1] = c1;
    if (offd) {
        float cs = butterfly32_(ccol, lane);   // lane l holds slot l = jg*8+q
        const int col = (jw * 4 + (lane >> 3)) * 16 + wc2 * 8 + (lane & 7);
        scol[rhalf][col] = cs;
    }
    __syncthreads();
    if (tid < 128) {
        float c = cred[0][tid] + cred[1][tid] + cred[2][tid] + cred[3][tid];
        atomicAdd(&g_c[b * NN + ti * 128 + tid], c);
        if (offd) atomicAdd(&g_c[colbase + tid], scol[0][tid] + scol[1][tid]);
    }
}

// ---------------------------------------------------------------------------
// K5: out[n,m] = g*(p_n*d_m + p_m*d_n) + [n==m]*d_n*d_m,
//     p = 0.5*w*d, d = rsqrt(0.5*c + 1.5).
// Streaming (__stcs) stores keep g_G resident in L2. Two half-phase hoists
// + occupancy 3 blocks/SM. Direct stores 32B-sector aligned; mirror stores
// column-contiguous float2 (256B/warp).
// ---------------------------------------------------------------------------
__global__ void __launch_bounds__(256, 3) k5_out(float* __restrict__ out) {
    __shared__ float dcs[128];
    __shared__ float pcs[128];
    TILE_IDX2();
    if (tid < 128) {
        float wm = 1.0f / g_s[colbase + tid];
        float dm = rsq_(fmaf(0.5f, g_c[colbase + tid], 1.5f));
        dcs[tid] = dm;
        pcs[tid] = 0.5f * wm * dm;
    }
    const float d0 = rsq_(fmaf(0.5f, g_c[growR], 1.5f));
    const float d1 = rsq_(fmaf(0.5f, g_c[growR + 1], 1.5f));
    const float p0 = 0.5f * d0 / g_s[growR];
    const float p1 = 0.5f * d1 / g_s[growR + 1];
    const int n0 = ti * 128 + nloc;
    const int m0 = tj * 128;
    float* ob = out + ((size_t)b << 20);
    __syncthreads();

    #pragma unroll
    for (int s = 0; s < 2; s++) {
        LOAD_G_HALF(s);
        #pragma unroll
        for (int jj = 0; jj < 2; jj++) {
            const int cb = (jw * 4 + s * 2 + jj) * 16 + wc2 * 8;
            UNPACK_G(jj);
            float v0[8], v1[8];
            #pragma unroll
            for (int q = 0; q < 8; q++) {
                const float dm = dcs[cb + q], pm = pcs[cb + q];
                v0[q] = a0[q] * fmaf(p0, dm, pm * d0);
                v1[q] = a1[q] * fmaf(p1, dm, pm * d1);
                if (!offd) {   // diagonal tile: self-loop term (tile-local compare)
                    if (nloc == cb + q)     v0[q] = fmaf(d0, dm, v0[q]);
                    if (nloc + 1 == cb + q) v1[q] = fmaf(d1, dm, v1[q]);
                }
            }
            float* r0 = ob + (size_t)n0 * NN + m0 + cb;
            float* r1 = ob + (size_t)(n0 + 1) * NN + m0 + cb;
            __stcs((float4*)(r0),     make_float4(v0[0], v0[1], v0[2], v0[3]));
            __stcs((float4*)(r0 + 4), make_float4(v0[4], v0[5], v0[6], v0[7]));
            __stcs((float4*)(r1),     make_float4(v1[0], v1[1], v1[2], v1[3]));
            __stcs((float4*)(r1 + 4), make_float4(v1[4], v1[5], v1[6], v1[7]));
            if (offd) {
                #pragma unroll
                for (int q = 0; q < 8; q++)
                    __stcs((float2*)(ob + (size_t)(m0 + cb + q) * NN + n0),
                           make_float2(v0[q], v1[q]));
            }
        }
    }
}

// ---------------------------------------------------------------------------
extern "C" void kernel_launch(void* const* d_in, const int* in_sizes, int n_in,
                              void* d_out, int out_size)
{
    const float* xt = (const float*)d_in[0];   // (32, 1024, 64)
    const float* W  = (const float*)d_in[1];   // (64, 24)
    const float* bv = (const float*)d_in[2];   // (24,)
    float* out = (float*)d_out;                // (32, 1024, 1024)

    k1_linrelu<<<512, 256>>>(xt, W, bv);
    k2_gram<<<BB * 36, 256>>>();
    k3_colsum<<<BB * 36, 256>>>();
    k5_out<<<BB * 36, 256>>>(out);
}

// round 10
// speedup vs baseline: 1.1390x; 1.1390x over previous
#include <cuda_runtime.h>
#include <math.h>

#define BB 32
#define NN 1024
#define FF 64
#define HH 24
#define L2E 1.4426950408889634f

// Scratch (allocation-free: __device__ globals)
__device__ float g_Z[BB * NN * HH];       // relu(linear) activations, 3 MB
__device__ float g_G[BB * 36 * 16384];    // lower-tri tiles of g=exp2(aL-C), K2-thread-order, 75.5 MB
__device__ float g_s[BB * NN];            // S_n = sum_m g (atomic accum)
__device__ float g_c[BB * NN];            // c_n = sum_m P_mn (atomic accum)
__device__ int   g_M[BB];                 // per-batch max row norm (bits; atomicMax replay-idempotent)

static __device__ __forceinline__ float ex2f_(float x) {
    float r; asm("ex2.approx.ftz.f32 %0, %1;" : "=f"(r) : "f"(x)); return r;
}
static __device__ __forceinline__ float rsq_(float x) {
    float r; asm("rsqrt.approx.f32 %0, %1;" : "=f"(r) : "f"(x)); return r;
}

// Butterfly transpose-reduce: 32 per-thread slot partials -> lane l holds the
// 32-lane sum of slot l (identity slot mapping; verified rounds 5-9).
static __device__ __forceinline__ float butterfly32_(float* c, int lane) {
    #pragma unroll
    for (int m = 16; m >= 1; m >>= 1) {
        const bool hi = (lane & m) != 0;
        #pragma unroll
        for (int i = 0; i < m; i++) {
            float sent = hi ? c[i] : c[i + m];
            float recv = __shfl_xor_sync(0xffffffffu, sent, m);
            c[i] = (hi ? c[i + m] : c[i]) + recv;
        }
    }
    return c[0];
}

// ---------------------------------------------------------------------------
// K1: Z = relu(xt @ W + b), batch max norm M_b; also zeroes g_s/g_c.
// ---------------------------------------------------------------------------
__global__ void __launch_bounds__(256) k1_linrelu(
    const float* __restrict__ xt, const float* __restrict__ W,
    const float* __restrict__ bias)
{
    __shared__ float xs[64][65];
    __shared__ float Ws[FF][HH];
    __shared__ float bs[HH];
    const int tid = threadIdx.x;
    const int base = blockIdx.x * 64;

    if (tid < 64) {                       // 512 blocks x 64 = 32768: zero accumulators
        g_s[base + tid] = 0.f;
        g_c[base + tid] = 0.f;
    }

    const float4* xt4 = (const float4*)(xt + (size_t)base * FF);
    for (int i = tid; i < 1024; i += 256) {
        float4 v = xt4[i];
        int row = i >> 4, c = (i & 15) << 2;
        xs[row][c] = v.x; xs[row][c + 1] = v.y; xs[row][c + 2] = v.z; xs[row][c + 3] = v.w;
    }
    for (int i = tid; i < FF * HH; i += 256) Ws[i / HH][i % HH] = W[i];
    if (tid < HH) bs[tid] = bias[tid];
    __syncthreads();

    const int row = tid >> 2, hg = tid & 3, h0 = hg * 6;
    float acc[6];
    #pragma unroll
    for (int j = 0; j < 6; j++) acc[j] = bs[h0 + j];
    #pragma unroll 8
    for (int k = 0; k < FF; k++) {
        float xa = xs[row][k];
        #pragma unroll
        for (int j = 0; j < 6; j++) acc[j] = fmaf(xa, Ws[k][h0 + j], acc[j]);
    }
    const int g = base + row;
    float ss = 0.f;
    #pragma unroll
    for (int j = 0; j < 6; j++) {
        float z = fmaxf(acc[j], 0.f);
        g_Z[(size_t)g * HH + h0 + j] = z;
        ss = fmaf(z, z, ss);
    }
    ss += __shfl_xor_sync(0xffffffffu, ss, 1);
    ss += __shfl_xor_sync(0xffffffffu, ss, 2);
    if (hg == 0) {
        float rn = sqrtf(ss);
        atomicMax(&g_M[base >> 10], __float_as_int(rn));  // rn>=0: int order == float order
    }
}

// ---------------------------------------------------------------------------
// Common triangular tile indices. grid = BB*36; t -> (ti, tj), ti >= tj.
// ---------------------------------------------------------------------------
#define TILE_COMMON() \
    const int tid = threadIdx.x, w = tid >> 5, lane = tid & 31;      \
    const int b = blockIdx.x / 36, t = blockIdx.x % 36;              \
    int ti = (int)((sqrtf(8.f * t + 1.f) - 1.f) * 0.5f);             \
    while ((ti + 1) * (ti + 2) / 2 <= t) ti++;                       \
    while (ti * (ti + 1) / 2 > t) ti--;                              \
    const int tj = t - ti * (ti + 1) / 2;                            \
    const int colbase = b * NN + tj * 128;                           \
    float* gtile = g_G + ((size_t)blockIdx.x << 14);                 \
    const bool offd = (ti != tj);

// K2 (producer) warp decomposition: 8 warps = rhalf(2) x wc(4)
#define TILE_IDX() \
    TILE_COMMON();                                                   \
    const int rhalf = w >> 2, wc = w & 3;                            \
    const int nloc = rhalf * 64 + lane * 2;                          \
    const int growR = b * NN + ti * 128 + nloc;

// K3 consumer warp decomposition: 8 warps = rhalf(2) x wc2(2) x jw(2).
#define TILE_IDX2() \
    TILE_COMMON();                                                   \
    const int rhalf = w >> 2, wc2 = w & 1, jw = (w >> 1) & 1;        \
    const int nloc = rhalf * 64 + lane * 2;                          \
    const int growR = b * NN + ti * 128 + nloc;

#define TILE_ZR() \
    float zr[2][24];                                                 \
    {                                                                \
        const float4* zg = (const float4*)g_Z;                       \
        _Pragma("unroll")                                            \
        for (int r = 0; r < 2; r++) {                                \
            _Pragma("unroll")                                        \
            for (int kk = 0; kk < 6; kk++) {                         \
                float4 v = zg[(size_t)(growR + r) * 6 + kk];         \
                zr[r][kk * 4 + 0] = v.x; zr[r][kk * 4 + 1] = v.y;    \
                zr[r][kk * 4 + 2] = v.z; zr[r][kk * 4 + 3] = v.w;    \
            }                                                        \
        }                                                            \
    }

#define GRAM_DOT(cb)                                                 \
    float a[2][4] = {};                                              \
    {                                                                \
        _Pragma("unroll")                                            \
        for (int kk = 0; kk < 6; kk++) {                             \
            float4 bq[4];                                            \
            _Pragma("unroll")                                        \
            for (int q = 0; q < 4; q++) bq[q] = Zc4[((cb) + q) * 6 + kk]; \
            _Pragma("unroll")                                        \
            for (int r = 0; r < 2; r++) {                            \
                _Pragma("unroll")                                    \
                for (int q = 0; q < 4; q++) {                        \
                    a[r][q] = fmaf(zr[r][kk * 4 + 0], bq[q].x, a[r][q]); \
                    a[r][q] = fmaf(zr[r][kk * 4 + 1], bq[q].y, a[r][q]); \
                    a[r][q] = fmaf(zr[r][kk * 4 + 2], bq[q].z, a[r][q]); \
                    a[r][q] = fmaf(zr[r][kk * 4 + 3], bq[q].w, a[r][q]); \
                }                                                    \
            }                                                        \
        }                                                            \
    }

// K3 half-hoist: 8 float4s covering jj = s*2, s*2+1.
#define LOAD_G_HALF(s)                                               \
    float4 G[2][4];                                                  \
    {                                                                \
        const float4* gp = (const float4*)gtile;                     \
        _Pragma("unroll")                                            \
        for (int jj = 0; jj < 2; jj++) {                             \
            const int j = jw * 4 + (s) * 2 + jj;                     \
            const int b4 = (j * 256 + (rhalf * 4 + wc2 * 2) * 32 + lane) * 2; \
            G[jj][0] = gp[b4];      G[jj][1] = gp[b4 + 1];           \
            G[jj][2] = gp[b4 + 64]; G[jj][3] = gp[b4 + 65];          \
        }                                                            \
    }

#define UNPACK_G(jj)                                                 \
    float a0[8], a1[8];                                              \
    a0[0] = G[jj][0].x; a0[1] = G[jj][0].y; a0[2] = G[jj][0].z; a0[3] = G[jj][0].w; \
    a0[4] = G[jj][2].x; a0[5] = G[jj][2].y; a0[6] = G[jj][2].z; a0[7] = G[jj][2].w; \
    a1[0] = G[jj][1].x; a1[1] = G[jj][1].y; a1[2] = G[jj][1].z; a1[3] = G[jj][1].w; \
    a1[4] = G[jj][3].x; a1[5] = G[jj][3].y; a1[6] = G[jj][3].z; a1[7] = G[jj][3].w;

// ---------------------------------------------------------------------------
// K2: the only gram pass. a = <Z_n,Z_m>; g = exp2(a*L2E - C), C = M_b^2*L2E
// (g <= 1, S <= 1024: overflow-free). Stores g; accumulates S_n row-side
// (regs) and, off-diag, col-side via register partials + butterfly.
// ---------------------------------------------------------------------------
__global__ void __launch_bounds__(256) k2_gram() {
    __shared__ float Zc[128 * 24];
    __shared__ float sred[4][128];
    __shared__ float scol[2][128];
    float4* Zc4 = (float4*)Zc;
    TILE_IDX();
    TILE_ZR();
    const float M = __int_as_float(g_M[b]);
    const float C = M * M * L2E;
    {
        const float4* src = (const float4*)(g_Z + (size_t)colbase * HH);
        for (int i = tid; i < 768; i += 256) Zc4[i] = src[i];
    }
    float s0 = 0.f, s1 = 0.f;
    float ccol[32];
    #pragma unroll
    for (int i = 0; i < 32; i++) ccol[i] = 0.f;
    __syncthreads();

    #pragma unroll 2
    for (int j = 0; j < 8; j++) {
        const int cb = wc * 4 + j * 16;
        GRAM_DOT(cb);
        float g0[4], g1[4];
        #pragma unroll
        for (int q = 0; q < 4; q++) {
            g0[q] = ex2f_(fmaf(a[0][q], L2E, -C));
            g1[q] = ex2f_(fmaf(a[1][q], L2E, -C));
        }
        float4* gp = (float4*)(gtile + ((j * 256 + tid) << 3));
        gp[0] = make_float4(g0[0], g0[1], g0[2], g0[3]);
        gp[1] = make_float4(g1[0], g1[1], g1[2], g1[3]);
        #pragma unroll
        for (int q = 0; q < 4; q++) {
            s0 += g0[q];
            s1 += g1[q];
            ccol[j * 4 + q] += g0[q] + g1[q];
        }
    }
    sred[wc][nloc] = s0;
    sred[wc][nloc + 1] = s1;
    if (offd) {
        float cs = butterfly32_(ccol, lane);   // lane l holds slot l = j*4+q
        scol[rhalf][wc * 4 + (lane & 3) + 16 * (lane >> 2)] = cs;
    }
    __syncthreads();
    if (tid < 128) {
        float s = sred[0][tid] + sred[1][tid] + sred[2][tid] + sred[3][tid];
        atomicAdd(&g_s[b * NN + ti * 128 + tid], s);
        if (offd) atomicAdd(&g_s[colbase + tid], scol[0][tid] + scol[1][tid]);
    }
}

// ---------------------------------------------------------------------------
// K3: column sums of P from stored g. P_nm = g*w_n, w = 1/S.
// ---------------------------------------------------------------------------
__global__ void __launch_bounds__(256) k3_colsum() {
    __shared__ float wv[128];
    __shared__ float cred[4][128];
    __shared__ float scol[2][128];
    TILE_IDX2();
    if (tid < 128) wv[tid] = 1.0f / g_s[colbase + tid];
    const float w0 = 1.0f / g_s[growR];
    const float w1 = 1.0f / g_s[growR + 1];
    float c0 = 0.f, c1 = 0.f;
    float ccol[32];
    #pragma unroll
    for (int i = 0; i < 32; i++) ccol[i] = 0.f;
    __syncthreads();

    #pragma unroll
    for (int s = 0; s < 2; s++) {
        LOAD_G_HALF(s);
        #pragma unroll
        for (int jj = 0; jj < 2; jj++) {
            const int jg = s * 2 + jj;
            const int cb = (jw * 4 + jg) * 16 + wc2 * 8;
            UNPACK_G(jj);
            #pragma unroll
            for (int q = 0; q < 8; q++) {
                float wm = wv[cb + q];
                c0 = fmaf(a0[q], wm, c0);
                c1 = fmaf(a1[q], wm, c1);
                ccol[jg * 8 + q] += fmaf(a0[q], w0, a1[q] * w1);
            }
        }
    }
    cred[w & 3][nloc] = c0;
    cred[w & 3][nloc + 1] = c1;
    if (offd) {
        float cs = butterfly32_(ccol, lane);   // lane l holds slot l = jg*8+q
        const int col = (jw * 4 + (lane >> 3)) * 16 + wc2 * 8 + (lane & 7);
        scol[rhalf][col] = cs;
    }
    __syncthreads();
    if (tid < 128) {
        float c = cred[0][tid] + cred[1][tid] + cred[2][tid] + cred[3][tid];
        atomicAdd(&g_c[b * NN + ti * 128 + tid], c);
        if (offd) atomicAdd(&g_c[colbase + tid], scol[0][tid] + scol[1][tid]);
    }
}

// ---------------------------------------------------------------------------
// K5: out[n,m] = g*(p_n*d_m + p_m*d_n) + [n==m]*d_n*d_m,
//     p = 0.5*w*d, d = rsqrt(0.5*c + 1.5).
// SMEM-staged: per 64-row half-tile phase, load g coalesced (native order),
// STS row-major padded (conflict-free), then:
//   direct: warp writes full 512B rows (1 STG.128 wavefront per row)
//   mirror: lanes take stride-32 columns (4-way LDS, 128B STG.32 wavefronts)
// ---------------------------------------------------------------------------
__global__ void __launch_bounds__(256) k5_out(float* __restrict__ out) {
    __shared__ float gsm[64 * 132];        // half-tile, row-major, padded
    __shared__ float dI[128], pI[128], dJ[128], pJ[128];
    TILE_COMMON();

    if (tid < 128) {
        int gi = b * NN + ti * 128 + tid;
        float d = rsq_(fmaf(0.5f, g_c[gi], 1.5f));
        dI[tid] = d; pI[tid] = 0.5f * d / g_s[gi];
        int gj = colbase + tid;
        float d2 = rsq_(fmaf(0.5f, g_c[gj], 1.5f));
        dJ[tid] = d2; pJ[tid] = 0.5f * d2 / g_s[gj];
    }
    float* ob = out + ((size_t)b << 20);
    __syncthreads();

    // col-side params for direct rows (reused across all rows/phases)
    const float4 dJv = *(const float4*)&dJ[lane * 4];
    const float4 pJv = *(const float4*)&pJ[lane * 4];

    #pragma unroll
    for (int ph = 0; ph < 2; ph++) {
        // --- stage rows [ph*64, ph*64+64) into row-major smem ---
        {
            const float4* gp4 = (const float4*)gtile;
            #pragma unroll
            for (int k = 0; k < 8; k++) {
                const int f = k * 512 + ph * 256 + tid;   // float4 index, coalesced
                float4 v = gp4[f];
                const int pi = f >> 1, r = f & 1;
                const int j = pi >> 8, w2 = (pi >> 5) & 7, lk = pi & 31;
                const int rl = lk * 2 + r;                // local row 0..63
                const int col = (w2 & 3) * 4 + j * 16;
                *(float4*)&gsm[rl * 132 + col] = v;       // bank-stride 33: conflict-free
            }
        }
        __syncthreads();

        // --- direct: rows R = ti*128 + ph*64 + w*8 + rr, full-row stores ---
        {
            const int rbase = ph * 64 + w * 8;
            #pragma unroll
            for (int rr = 0; rr < 8; rr++) {
                const int Rl = rbase + rr;                // tile-local row
                const float dn = dI[Rl], pn = pI[Rl];
                float4 g4 = *(const float4*)&gsm[(w * 8 + rr) * 132 + lane * 4];
                float4 v;
                v.x = g4.x * fmaf(pn, dJv.x, pJv.x * dn);
                v.y = g4.y * fmaf(pn, dJv.y, pJv.y * dn);
                v.z = g4.z * fmaf(pn, dJv.z, pJv.z * dn);
                v.w = g4.w * fmaf(pn, dJv.w, pJv.w * dn);
                if (!offd && lane == (Rl >> 2)) {         // diagonal element (Rl&3 == rr&3)
                    const float add = dn * dJ[Rl];
                    if ((rr & 3) == 0) v.x += add;
                    else if ((rr & 3) == 1) v.y += add;
                    else if ((rr & 3) == 2) v.z += add;
                    else v.w += add;
                }
                __stcs((float4*)(ob + (size_t)(ti * 128 + Rl) * NN + tj * 128 + lane * 4), v);
            }
        }

        // --- mirror: output rows Rm = w*16+rr, cols ti*128 + ph*64 + lane + 32u ---
        if (offd) {
            const float dn0 = dI[ph * 64 + lane],      pn0 = pI[ph * 64 + lane];
            const float dn1 = dI[ph * 64 + lane + 32], pn1 = pI[ph * 64 + lane + 32];
            #pragma unroll
            for (int rr = 0; rr < 16; rr++) {
                const int Rm = w * 16 + rr;
                const float dm = dJ[Rm], pm = pJ[Rm];
                const float gA = gsm[lane * 132 + Rm];         // 4-way conflict, acceptable
                const float gB = gsm[(lane + 32) * 132 + Rm];
                const float vA = gA * fmaf(pm, dn0, pn0 * dm);
                const float vB = gB * fmaf(pm, dn1, pn1 * dm);
                float* mrow = ob + (size_t)(tj * 128 + Rm) * NN + ti * 128 + ph * 64;
                __stcs(mrow + lane, vA);
                __stcs(mrow + lane + 32, vB);
            }
        }
        __syncthreads();
    }
}

// ---------------------------------------------------------------------------
extern "C" void kernel_launch(void* const* d_in, const int* in_sizes, int n_in,
                              void* d_out, int out_size)
{
    const float* xt = (const float*)d_in[0];   // (32, 1024, 64)
    const float* W  = (const float*)d_in[1];   // (64, 24)
    const float* bv = (const float*)d_in[2];   // (24,)
    float* out = (float*)d_out;                // (32, 1024, 1024)

    k1_linrelu<<<512, 256>>>(xt, W, bv);
    k2_gram<<<BB * 36, 256>>>();
    k3_colsum<<<BB * 36, 256>>>();
    k5_out<<<BB * 36, 256>>>(out);
}

// round 13
// speedup vs baseline: 1.1897x; 1.0445x over previous
#include <cuda_runtime.h>
#include <cstdint>
#include <math.h>

#define BB 32
#define NN 1024
#define FF 64
#define HH 24
#define L2E 1.4426950408889634f

// Scratch (allocation-free: __device__ globals)
__device__ float g_Z[BB * NN * HH];       // relu(linear) activations, 3 MB
__device__ float g_G[BB * 36 * 16384];    // lower-tri tiles of g=exp2(aL-C), K2-chunk order, 75.5 MB
__device__ float g_s[BB * NN];            // S_n = sum_m g (atomic accum)
__device__ float g_c[BB * NN];            // c_n = sum_m P_mn (atomic accum)
__device__ int   g_M[BB];                 // per-batch max row norm (bits; atomicMax replay-idempotent)

static __device__ __forceinline__ float ex2f_(float x) {
    float r; asm("ex2.approx.ftz.f32 %0, %1;" : "=f"(r) : "f"(x)); return r;
}
static __device__ __forceinline__ float rsq_(float x) {
    float r; asm("rsqrt.approx.f32 %0, %1;" : "=f"(r) : "f"(x)); return r;
}

// Butterfly transpose-reduce: 32 per-thread slot partials -> lane l holds the
// 32-lane sum of slot l (identity slot mapping; verified rounds 5-10).
static __device__ __forceinline__ float butterfly32_(float* c, int lane) {
    #pragma unroll
    for (int m = 16; m >= 1; m >>= 1) {
        const bool hi = (lane & m) != 0;
        #pragma unroll
        for (int i = 0; i < m; i++) {
            float sent = hi ? c[i] : c[i + m];
            float recv = __shfl_xor_sync(0xffffffffu, sent, m);
            c[i] = (hi ? c[i + m] : c[i]) + recv;
        }
    }
    return c[0];
}

// ---------------------------------------------------------------------------
// K1: Z = relu(xt @ W + b), batch max norm M_b; also zeroes g_s/g_c.
// ---------------------------------------------------------------------------
__global__ void __launch_bounds__(256) k1_linrelu(
    const float* __restrict__ xt, const float* __restrict__ W,
    const float* __restrict__ bias)
{
    __shared__ float xs[64][65];
    __shared__ float Ws[FF][HH];
    __shared__ float bs[HH];
    const int tid = threadIdx.x;
    const int base = blockIdx.x * 64;

    if (tid < 64) {                       // 512 blocks x 64 = 32768: zero accumulators
        g_s[base + tid] = 0.f;
        g_c[base + tid] = 0.f;
    }

    const float4* xt4 = (const float4*)(xt + (size_t)base * FF);
    for (int i = tid; i < 1024; i += 256) {
        float4 v = xt4[i];
        int row = i >> 4, c = (i & 15) << 2;
        xs[row][c] = v.x; xs[row][c + 1] = v.y; xs[row][c + 2] = v.z; xs[row][c + 3] = v.w;
    }
    for (int i = tid; i < FF * HH; i += 256) Ws[i / HH][i % HH] = W[i];
    if (tid < HH) bs[tid] = bias[tid];
    __syncthreads();

    const int row = tid >> 2, hg = tid & 3, h0 = hg * 6;
    float acc[6];
    #pragma unroll
    for (int j = 0; j < 6; j++) acc[j] = bs[h0 + j];
    #pragma unroll 8
    for (int k = 0; k < FF; k++) {
        float xa = xs[row][k];
        #pragma unroll
        for (int j = 0; j < 6; j++) acc[j] = fmaf(xa, Ws[k][h0 + j], acc[j]);
    }
    const int g = base + row;
    float ss = 0.f;
    #pragma unroll
    for (int j = 0; j < 6; j++) {
        float z = fmaxf(acc[j], 0.f);
        g_Z[(size_t)g * HH + h0 + j] = z;
        ss = fmaf(z, z, ss);
    }
    ss += __shfl_xor_sync(0xffffffffu, ss, 1);
    ss += __shfl_xor_sync(0xffffffffu, ss, 2);
    if (hg == 0) {
        float rn = sqrtf(ss);
        atomicMax(&g_M[base >> 10], __float_as_int(rn));  // rn>=0: int order == float order
    }
}

// ---------------------------------------------------------------------------
// Common triangular tile indices. grid = BB*36; t -> (ti, tj), ti >= tj.
// ---------------------------------------------------------------------------
#define TILE_COMMON() \
    const int tid = threadIdx.x, w = tid >> 5, lane = tid & 31;      \
    const int b = blockIdx.x / 36, t = blockIdx.x % 36;              \
    int ti = (int)((sqrtf(8.f * t + 1.f) - 1.f) * 0.5f);             \
    while ((ti + 1) * (ti + 2) / 2 <= t) ti++;                       \
    while (ti * (ti + 1) / 2 > t) ti--;                              \
    const int tj = t - ti * (ti + 1) / 2;                            \
    const int colbase = b * NN + tj * 128;                           \
    float* gtile = g_G + ((size_t)blockIdx.x << 14);                 \
    const bool offd = (ti != tj);

// K3 consumer warp decomposition: 8 warps = rhalf(2) x wc2(2) x jw(2).
#define TILE_IDX2() \
    TILE_COMMON();                                                   \
    const int rhalf = w >> 2, wc2 = w & 1, jw = (w >> 1) & 1;        \
    const int nloc = rhalf * 64 + lane * 2;                          \
    const int growR = b * NN + ti * 128 + nloc;

// K3 half-hoist: 8 float4s covering jj = s*2, s*2+1.
#define LOAD_G_HALF(s)                                               \
    float4 G[2][4];                                                  \
    {                                                                \
        const float4* gp = (const float4*)gtile;                     \
        _Pragma("unroll")                                            \
        for (int jj = 0; jj < 2; jj++) {                             \
            const int j = jw * 4 + (s) * 2 + jj;                     \
            const int b4 = (j * 256 + (rhalf * 4 + wc2 * 2) * 32 + lane) * 2; \
            G[jj][0] = gp[b4];      G[jj][1] = gp[b4 + 1];           \
            G[jj][2] = gp[b4 + 64]; G[jj][3] = gp[b4 + 65];          \
        }                                                            \
    }

#define UNPACK_G(jj)                                                 \
    float a0[8], a1[8];                                              \
    a0[0] = G[jj][0].x; a0[1] = G[jj][0].y; a0[2] = G[jj][0].z; a0[3] = G[jj][0].w; \
    a0[4] = G[jj][2].x; a0[5] = G[jj][2].y; a0[6] = G[jj][2].z; a0[7] = G[jj][2].w; \
    a1[0] = G[jj][1].x; a1[1] = G[jj][1].y; a1[2] = G[jj][1].z; a1[3] = G[jj][1].w; \
    a1[4] = G[jj][3].x; a1[5] = G[jj][3].y; a1[6] = G[jj][3].z; a1[7] = G[jj][3].w;

// ---------------------------------------------------------------------------
// K2: the only gram pass (FFMA; tcgen05 unavailable: harness targets sm_100
// PTX). 128 threads, 4 warps = wc. Thread owns 4 rows {2l, 2l+1, 2l+64,
// 2l+65} (warp spans all 128 rows -> no duplicated column LDS); warp w owns
// cols cb = w*4 + j*16, j=0..7. g = exp2(a*L2E - C), C = M_b^2*L2E, stored
// in the legacy K2-chunk layout (k3/k5 unchanged).
// ---------------------------------------------------------------------------
__global__ void __launch_bounds__(128) k2_gram() {
    __shared__ float Zc[128 * 24];
    __shared__ float sred[4][128];
    float4* Zc4 = (float4*)Zc;
    TILE_COMMON();

    const float M = __int_as_float(g_M[b]);
    const float C = M * M * L2E;

    // Stage column-side Z (rows of tile tj): 12 KB
    {
        const float4* src = (const float4*)(g_Z + (size_t)colbase * HH);
        #pragma unroll
        for (int i = 0; i < 6; i++) Zc4[i * 128 + tid] = src[i * 128 + tid];
    }

    // Register-resident row-side Z: 4 rows/thread
    float zr[4][24];
    {
        const float4* zg = (const float4*)g_Z;
        const int rbase = b * NN + ti * 128;
        #pragma unroll
        for (int r = 0; r < 4; r++) {
            const int R = (r & 1) + 2 * lane + (r >> 1) * 64;
            #pragma unroll
            for (int kk = 0; kk < 6; kk++) {
                float4 v = zg[(size_t)(rbase + R) * 6 + kk];
                zr[r][kk * 4 + 0] = v.x; zr[r][kk * 4 + 1] = v.y;
                zr[r][kk * 4 + 2] = v.z; zr[r][kk * 4 + 3] = v.w;
            }
        }
    }
    float s[4] = {0.f, 0.f, 0.f, 0.f};
    float ccol[32];
    #pragma unroll
    for (int i = 0; i < 32; i++) ccol[i] = 0.f;
    __syncthreads();

    float4* gt4 = (float4*)gtile;
    #pragma unroll 2
    for (int j = 0; j < 8; j++) {
        const int cb = w * 4 + j * 16;
        float a[4][4];
        #pragma unroll
        for (int r = 0; r < 4; r++)
            #pragma unroll
            for (int q = 0; q < 4; q++) a[r][q] = 0.f;
        #pragma unroll
        for (int kk = 0; kk < 6; kk++) {
            float4 bq[4];
            #pragma unroll
            for (int q = 0; q < 4; q++) bq[q] = Zc4[(cb + q) * 6 + kk];
            #pragma unroll
            for (int r = 0; r < 4; r++) {
                #pragma unroll
                for (int q = 0; q < 4; q++) {
                    a[r][q] = fmaf(zr[r][kk * 4 + 0], bq[q].x, a[r][q]);
                    a[r][q] = fmaf(zr[r][kk * 4 + 1], bq[q].y, a[r][q]);
                    a[r][q] = fmaf(zr[r][kk * 4 + 2], bq[q].z, a[r][q]);
                    a[r][q] = fmaf(zr[r][kk * 4 + 3], bq[q].w, a[r][q]);
                }
            }
        }
        // exp, store (legacy layout: F = j*512 + (rhalf*4+w)*64 + 2*lane + r
        // -- contiguous across the warp), accumulate row/col sums
        #pragma unroll
        for (int r = 0; r < 4; r++) {
            float g0 = ex2f_(fmaf(a[r][0], L2E, -C));
            float g1 = ex2f_(fmaf(a[r][1], L2E, -C));
            float g2 = ex2f_(fmaf(a[r][2], L2E, -C));
            float g3 = ex2f_(fmaf(a[r][3], L2E, -C));
            const int F = j * 512 + ((r >> 1) * 4 + w) * 64 + 2 * lane + (r & 1);
            gt4[F] = make_float4(g0, g1, g2, g3);
            s[r] += g0 + g1 + g2 + g3;
            ccol[j * 4 + 0] += g0;
            ccol[j * 4 + 1] += g1;
            ccol[j * 4 + 2] += g2;
            ccol[j * 4 + 3] += g3;
        }
    }

    // Row sums: 4 warps (disjoint col ranges) reduced via smem
    sred[w][2 * lane]      = s[0];
    sred[w][2 * lane + 1]  = s[1];
    sred[w][2 * lane + 64] = s[2];
    sred[w][2 * lane + 65] = s[3];
    // Col sums: warp spans all 128 rows and warps own disjoint cols ->
    // butterfly then direct atomicAdd (lane l holds slot l = j*4+q)
    if (offd) {
        float cs = butterfly32_(ccol, lane);
        const int col = w * 4 + (lane & 3) + 16 * (lane >> 2);
        atomicAdd(&g_s[colbase + col], cs);
    }
    __syncthreads();
    float srow = sred[0][tid] + sred[1][tid] + sred[2][tid] + sred[3][tid];
    atomicAdd(&g_s[b * NN + ti * 128 + tid], srow);
}

// ---------------------------------------------------------------------------
// K3: column sums of P from stored g. P_nm = g*w_n, w = 1/S.  (unchanged)
// ---------------------------------------------------------------------------
__global__ void __launch_bounds__(256) k3_colsum() {
    __shared__ float wv[128];
    __shared__ float cred[4][128];
    __shared__ float scol[2][128];
    TILE_IDX2();
    if (tid < 128) wv[tid] = 1.0f / g_s[colbase + tid];
    const float w0 = 1.0f / g_s[growR];
    const float w1 = 1.0f / g_s[growR + 1];
    float c0 = 0.f, c1 = 0.f;
    float ccol[32];
    #pragma unroll
    for (int i = 0; i < 32; i++) ccol[i] = 0.f;
    __syncthreads();

    #pragma unroll
    for (int s = 0; s < 2; s++) {
        LOAD_G_HALF(s);
        #pragma unroll
        for (int jj = 0; jj < 2; jj++) {
            const int jg = s * 2 + jj;
            const int cb = (jw * 4 + jg) * 16 + wc2 * 8;
            UNPACK_G(jj);
            #pragma unroll
            for (int q = 0; q < 8; q++) {
                float wm = wv[cb + q];
                c0 = fmaf(a0[q], wm, c0);
                c1 = fmaf(a1[q], wm, c1);
                ccol[jg * 8 + q] += fmaf(a0[q], w0, a1[q] * w1);
            }
        }
    }
    cred[w & 3][nloc] = c0;
    cred[w & 3][nloc + 1] = c1;
    if (offd) {
        float cs = butterfly32_(ccol, lane);   // lane l holds slot l = jg*8+q
        const int col = (jw * 4 + (lane >> 3)) * 16 + wc2 * 8 + (lane & 7);
        scol[rhalf][col] = cs;
    }
    __syncthreads();
    if (tid < 128) {
        float c = cred[0][tid] + cred[1][tid] + cred[2][tid] + cred[3][tid];
        atomicAdd(&g_c[b * NN + ti * 128 + tid], c);
        if (offd) atomicAdd(&g_c[colbase + tid], scol[0][tid] + scol[1][tid]);
    }
}

// ---------------------------------------------------------------------------
// K5: out[n,m] = g*(p_n*d_m + p_m*d_n) + [n==m]*d_n*d_m.  (unchanged)
// ---------------------------------------------------------------------------
__global__ void __launch_bounds__(256) k5_out(float* __restrict__ out) {
    __shared__ float gsm[64 * 132];        // half-tile, row-major, padded
    __shared__ float dI[128], pI[128], dJ[128], pJ[128];
    TILE_COMMON();

    if (tid < 128) {
        int gi = b * NN + ti * 128 + tid;
        float d = rsq_(fmaf(0.5f, g_c[gi], 1.5f));
        dI[tid] = d; pI[tid] = 0.5f * d / g_s[gi];
        int gj = colbase + tid;
        float d2 = rsq_(fmaf(0.5f, g_c[gj], 1.5f));
        dJ[tid] = d2; pJ[tid] = 0.5f * d2 / g_s[gj];
    }
    float* ob = out + ((size_t)b << 20);
    __syncthreads();

    const float4 dJv = *(const float4*)&dJ[lane * 4];
    const float4 pJv = *(const float4*)&pJ[lane * 4];

    #pragma unroll
    for (int ph = 0; ph < 2; ph++) {
        {
            const float4* gp4 = (const float4*)gtile;
            #pragma unroll
            for (int k = 0; k < 8; k++) {
                const int f = k * 512 + ph * 256 + tid;
                float4 v = gp4[f];
                const int pi = f >> 1, r = f & 1;
                const int j = pi >> 8, w2 = (pi >> 5) & 7, lk = pi & 31;
                const int rl = lk * 2 + r;
                const int col = (w2 & 3) * 4 + j * 16;
                *(float4*)&gsm[rl * 132 + col] = v;
            }
        }
        __syncthreads();

        {
            const int rbase = ph * 64 + w * 8;
            #pragma unroll
            for (int rr = 0; rr < 8; rr++) {
                const int Rl = rbase + rr;
                const float dn = dI[Rl], pn = pI[Rl];
                float4 g4 = *(const float4*)&gsm[(w * 8 + rr) * 132 + lane * 4];
                float4 v;
                v.x = g4.x * fmaf(pn, dJv.x, pJv.x * dn);
                v.y = g4.y * fmaf(pn, dJv.y, pJv.y * dn);
                v.z = g4.z * fmaf(pn, dJv.z, pJv.z * dn);
                v.w = g4.w * fmaf(pn, dJv.w, pJv.w * dn);
                if (!offd && lane == (Rl >> 2)) {
                    const float add = dn * dJ[Rl];
                    if ((rr & 3) == 0) v.x += add;
                    else if ((rr & 3) == 1) v.y += add;
                    else if ((rr & 3) == 2) v.z += add;
                    else v.w += add;
                }
                __stcs((float4*)(ob + (size_t)(ti * 128 + Rl) * NN + tj * 128 + lane * 4), v);
            }
        }

        if (offd) {
            const float dn0 = dI[ph * 64 + lane],      pn0 = pI[ph * 64 + lane];
            const float dn1 = dI[ph * 64 + lane + 32], pn1 = pI[ph * 64 + lane + 32];
            #pragma unroll
            for (int rr = 0; rr < 16; rr++) {
                const int Rm = w * 16 + rr;
                const float dm = dJ[Rm], pm = pJ[Rm];
                const float gA = gsm[lane * 132 + Rm];
                const float gB = gsm[(lane + 32) * 132 + Rm];
                const float vA = gA * fmaf(pm, dn0, pn0 * dm);
                const float vB = gB * fmaf(pm, dn1, pn1 * dm);
                float* mrow = ob + (size_t)(tj * 128 + Rm) * NN + ti * 128 + ph * 64;
                __stcs(mrow + lane, vA);
                __stcs(mrow + lane + 32, vB);
            }
        }
        __syncthreads();
    }
}

// ---------------------------------------------------------------------------
extern "C" void kernel_launch(void* const* d_in, const int* in_sizes, int n_in,
                              void* d_out, int out_size)
{
    const float* xt = (const float*)d_in[0];   // (32, 1024, 64)
    const float* W  = (const float*)d_in[1];   // (64, 24)
    const float* bv = (const float*)d_in[2];   // (24,)
    float* out = (float*)d_out;                // (32, 1024, 1024)

    k1_linrelu<<<512, 256>>>(xt, W, bv);
    k2_gram<<<BB * 36, 128>>>();
    k3_colsum<<<BB * 36, 256>>>();
    k5_out<<<BB * 36, 256>>>(out);
}

// round 14
// speedup vs baseline: 1.2170x; 1.0229x over previous
#include <cuda_runtime.h>
#include <cstdint>
#include <math.h>

#define BB 32
#define NN 1024
#define FF 64
#define HH 24
#define L2E 1.4426950408889634f

// Scratch (allocation-free: __device__ globals)
__device__ float g_Z[BB * NN * HH];       // relu(linear) activations, 3 MB
__device__ float g_G[BB * 36 * 16384];    // lower-tri tiles of g=exp2(aL-C), K2-chunk order, 75.5 MB
__device__ float g_s[BB * NN];            // S_n = sum_m g (atomic accum)
__device__ float g_c[BB * NN];            // c_n = sum_m P_mn (atomic accum)
__device__ int   g_M[BB];                 // per-batch max row norm (bits; atomicMax replay-idempotent)

static __device__ __forceinline__ float ex2f_(float x) {
    float r; asm("ex2.approx.ftz.f32 %0, %1;" : "=f"(r) : "f"(x)); return r;
}
static __device__ __forceinline__ float rsq_(float x) {
    float r; asm("rsqrt.approx.f32 %0, %1;" : "=f"(r) : "f"(x)); return r;
}
// Packed dual fp32 FMA (FFMA2). d.lo += a.lo*b.lo; d.hi += a.hi*b.hi.
static __device__ __forceinline__ void fma2_(unsigned long long& d,
                                             unsigned long long a,
                                             unsigned long long b) {
    asm("fma.rn.f32x2 %0, %1, %2, %0;" : "+l"(d) : "l"(a), "l"(b));
}

// Butterfly transpose-reduce: 32 per-thread slot partials -> lane l holds the
// 32-lane sum of slot l (identity slot mapping; verified rounds 5-13).
static __device__ __forceinline__ float butterfly32_(float* c, int lane) {
    #pragma unroll
    for (int m = 16; m >= 1; m >>= 1) {
        const bool hi = (lane & m) != 0;
        #pragma unroll
        for (int i = 0; i < m; i++) {
            float sent = hi ? c[i] : c[i + m];
            float recv = __shfl_xor_sync(0xffffffffu, sent, m);
            c[i] = (hi ? c[i + m] : c[i]) + recv;
        }
    }
    return c[0];
}

// ---------------------------------------------------------------------------
// K1: Z = relu(xt @ W + b), batch max norm M_b; also zeroes g_s/g_c.
// ---------------------------------------------------------------------------
__global__ void __launch_bounds__(256) k1_linrelu(
    const float* __restrict__ xt, const float* __restrict__ W,
    const float* __restrict__ bias)
{
    __shared__ float xs[64][65];
    __shared__ float Ws[FF][HH];
    __shared__ float bs[HH];
    const int tid = threadIdx.x;
    const int base = blockIdx.x * 64;

    if (tid < 64) {                       // 512 blocks x 64 = 32768: zero accumulators
        g_s[base + tid] = 0.f;
        g_c[base + tid] = 0.f;
    }

    const float4* xt4 = (const float4*)(xt + (size_t)base * FF);
    for (int i = tid; i < 1024; i += 256) {
        float4 v = xt4[i];
        int row = i >> 4, c = (i & 15) << 2;
        xs[row][c] = v.x; xs[row][c + 1] = v.y; xs[row][c + 2] = v.z; xs[row][c + 3] = v.w;
    }
    for (int i = tid; i < FF * HH; i += 256) Ws[i / HH][i % HH] = W[i];
    if (tid < HH) bs[tid] = bias[tid];
    __syncthreads();

    const int row = tid >> 2, hg = tid & 3, h0 = hg * 6;
    float acc[6];
    #pragma unroll
    for (int j = 0; j < 6; j++) acc[j] = bs[h0 + j];
    #pragma unroll 8
    for (int k = 0; k < FF; k++) {
        float xa = xs[row][k];
        #pragma unroll
        for (int j = 0; j < 6; j++) acc[j] = fmaf(xa, Ws[k][h0 + j], acc[j]);
    }
    const int g = base + row;
    float ss = 0.f;
    #pragma unroll
    for (int j = 0; j < 6; j++) {
        float z = fmaxf(acc[j], 0.f);
        g_Z[(size_t)g * HH + h0 + j] = z;
        ss = fmaf(z, z, ss);
    }
    ss += __shfl_xor_sync(0xffffffffu, ss, 1);
    ss += __shfl_xor_sync(0xffffffffu, ss, 2);
    if (hg == 0) {
        float rn = sqrtf(ss);
        atomicMax(&g_M[base >> 10], __float_as_int(rn));  // rn>=0: int order == float order
    }
}

// ---------------------------------------------------------------------------
// Common triangular tile indices. grid = BB*36; t -> (ti, tj), ti >= tj.
// ---------------------------------------------------------------------------
#define TILE_COMMON() \
    const int tid = threadIdx.x, w = tid >> 5, lane = tid & 31;      \
    const int b = blockIdx.x / 36, t = blockIdx.x % 36;              \
    int ti = (int)((sqrtf(8.f * t + 1.f) - 1.f) * 0.5f);             \
    while ((ti + 1) * (ti + 2) / 2 <= t) ti++;                       \
    while (ti * (ti + 1) / 2 > t) ti--;                              \
    const int tj = t - ti * (ti + 1) / 2;                            \
    const int colbase = b * NN + tj * 128;                           \
    float* gtile = g_G + ((size_t)blockIdx.x << 14);                 \
    const bool offd = (ti != tj);

// K3 consumer warp decomposition: 8 warps = rhalf(2) x wc2(2) x jw(2).
#define TILE_IDX2() \
    TILE_COMMON();                                                   \
    const int rhalf = w >> 2, wc2 = w & 1, jw = (w >> 1) & 1;        \
    const int nloc = rhalf * 64 + lane * 2;                          \
    const int growR = b * NN + ti * 128 + nloc;

// K3 half-hoist: 8 float4s covering jj = s*2, s*2+1.
#define LOAD_G_HALF(s)                                               \
    float4 G[2][4];                                                  \
    {                                                                \
        const float4* gp = (const float4*)gtile;                     \
        _Pragma("unroll")                                            \
        for (int jj = 0; jj < 2; jj++) {                             \
            const int j = jw * 4 + (s) * 2 + jj;                     \
            const int b4 = (j * 256 + (rhalf * 4 + wc2 * 2) * 32 + lane) * 2; \
            G[jj][0] = gp[b4];      G[jj][1] = gp[b4 + 1];           \
            G[jj][2] = gp[b4 + 64]; G[jj][3] = gp[b4 + 65];          \
        }                                                            \
    }

#define UNPACK_G(jj)                                                 \
    float a0[8], a1[8];                                              \
    a0[0] = G[jj][0].x; a0[1] = G[jj][0].y; a0[2] = G[jj][0].z; a0[3] = G[jj][0].w; \
    a0[4] = G[jj][2].x; a0[5] = G[jj][2].y; a0[6] = G[jj][2].z; a0[7] = G[jj][2].w; \
    a1[0] = G[jj][1].x; a1[1] = G[jj][1].y; a1[2] = G[jj][1].z; a1[3] = G[jj][1].w; \
    a1[4] = G[jj][3].x; a1[5] = G[jj][3].y; a1[6] = G[jj][3].z; a1[7] = G[jj][3].w;

// ---------------------------------------------------------------------------
// K2: the only gram pass (FFMA2 via fma.rn.f32x2 -- packed k-pairs, no
// packing overhead: both operands reinterpret float4 -> 2 x f32x2).
// 128 threads, 4 warps. Thread owns 4 rows {2l, 2l+1, 2l+64, 2l+65}; warp w
// owns cols cb = w*4 + j*16. g = exp2(a*L2E - C), C = M_b^2*L2E, stored in
// the legacy K2-chunk layout (k3/k5 unchanged).
// ---------------------------------------------------------------------------
union F4U2 { float4 f4; ulonglong2 u2; };

__global__ void __launch_bounds__(128) k2_gram() {
    __shared__ float Zc[128 * 24];
    __shared__ float sred[4][128];
    float4* Zc4 = (float4*)Zc;
    TILE_COMMON();

    const float M = __int_as_float(g_M[b]);
    const float C = M * M * L2E;

    // Stage column-side Z (rows of tile tj): 12 KB
    {
        const float4* src = (const float4*)(g_Z + (size_t)colbase * HH);
        #pragma unroll
        for (int i = 0; i < 6; i++) Zc4[i * 128 + tid] = src[i * 128 + tid];
    }

    // Register-resident row-side Z: 4 rows/thread, packed as 12 f32x2 per row
    unsigned long long zr2[4][12];
    {
        const float4* zg = (const float4*)g_Z;
        const int rbase = b * NN + ti * 128;
        #pragma unroll
        for (int r = 0; r < 4; r++) {
            const int R = (r & 1) + 2 * lane + (r >> 1) * 64;
            #pragma unroll
            for (int kk = 0; kk < 6; kk++) {
                F4U2 u; u.f4 = zg[(size_t)(rbase + R) * 6 + kk];
                zr2[r][2 * kk]     = u.u2.x;
                zr2[r][2 * kk + 1] = u.u2.y;
            }
        }
    }
    float s[4] = {0.f, 0.f, 0.f, 0.f};
    float ccol[32];
    #pragma unroll
    for (int i = 0; i < 32; i++) ccol[i] = 0.f;
    __syncthreads();

    float4* gt4 = (float4*)gtile;
    #pragma unroll 2
    for (int j = 0; j < 8; j++) {
        const int cb = w * 4 + j * 16;
        unsigned long long a2[4][4];
        #pragma unroll
        for (int r = 0; r < 4; r++)
            #pragma unroll
            for (int q = 0; q < 4; q++) a2[r][q] = 0ull;
        #pragma unroll
        for (int kk = 0; kk < 6; kk++) {
            F4U2 bq[4];
            #pragma unroll
            for (int q = 0; q < 4; q++) bq[q].f4 = Zc4[(cb + q) * 6 + kk];
            #pragma unroll
            for (int r = 0; r < 4; r++) {
                #pragma unroll
                for (int q = 0; q < 4; q++) {
                    fma2_(a2[r][q], zr2[r][2 * kk],     bq[q].u2.x);
                    fma2_(a2[r][q], zr2[r][2 * kk + 1], bq[q].u2.y);
                }
            }
        }
        // unpack (even,odd) partial pairs -> scalar a; exp; store legacy layout
        #pragma unroll
        for (int r = 0; r < 4; r++) {
            float av[4];
            #pragma unroll
            for (int q = 0; q < 4; q++) {
                float2 p = *reinterpret_cast<float2*>(&a2[r][q]);
                av[q] = p.x + p.y;
            }
            float g0 = ex2f_(fmaf(av[0], L2E, -C));
            float g1 = ex2f_(fmaf(av[1], L2E, -C));
            float g2 = ex2f_(fmaf(av[2], L2E, -C));
            float g3 = ex2f_(fmaf(av[3], L2E, -C));
            const int F = j * 512 + ((r >> 1) * 4 + w) * 64 + 2 * lane + (r & 1);
            gt4[F] = make_float4(g0, g1, g2, g3);
            s[r] += g0 + g1 + g2 + g3;
            ccol[j * 4 + 0] += g0;
            ccol[j * 4 + 1] += g1;
            ccol[j * 4 + 2] += g2;
            ccol[j * 4 + 3] += g3;
        }
    }

    // Row sums: 4 warps (disjoint col ranges) reduced via smem
    sred[w][2 * lane]      = s[0];
    sred[w][2 * lane + 1]  = s[1];
    sred[w][2 * lane + 64] = s[2];
    sred[w][2 * lane + 65] = s[3];
    // Col sums: warp spans all 128 rows; warps own disjoint cols
    if (offd) {
        float cs = butterfly32_(ccol, lane);   // lane l holds slot l = j*4+q
        const int col = w * 4 + (lane & 3) + 16 * (lane >> 2);
        atomicAdd(&g_s[colbase + col], cs);
    }
    __syncthreads();
    float srow = sred[0][tid] + sred[1][tid] + sred[2][tid] + sred[3][tid];
    atomicAdd(&g_s[b * NN + ti * 128 + tid], srow);
}

// ---------------------------------------------------------------------------
// K3: column sums of P from stored g. P_nm = g*w_n, w = 1/S.  (unchanged)
// ---------------------------------------------------------------------------
__global__ void __launch_bounds__(256) k3_colsum() {
    __shared__ float wv[128];
    __shared__ float cred[4][128];
    __shared__ float scol[2][128];
    TILE_IDX2();
    if (tid < 128) wv[tid] = 1.0f / g_s[colbase + tid];
    const float w0 = 1.0f / g_s[growR];
    const float w1 = 1.0f / g_s[growR + 1];
    float c0 = 0.f, c1 = 0.f;
    float ccol[32];
    #pragma unroll
    for (int i = 0; i < 32; i++) ccol[i] = 0.f;
    __syncthreads();

    #pragma unroll
    for (int s = 0; s < 2; s++) {
        LOAD_G_HALF(s);
        #pragma unroll
        for (int jj = 0; jj < 2; jj++) {
            const int jg = s * 2 + jj;
            const int cb = (jw * 4 + jg) * 16 + wc2 * 8;
            UNPACK_G(jj);
            #pragma unroll
            for (int q = 0; q < 8; q++) {
                float wm = wv[cb + q];
                c0 = fmaf(a0[q], wm, c0);
                c1 = fmaf(a1[q], wm, c1);
                ccol[jg * 8 + q] += fmaf(a0[q], w0, a1[q] * w1);
            }
        }
    }
    cred[w & 3][nloc] = c0;
    cred[w & 3][nloc + 1] = c1;
    if (offd) {
        float cs = butterfly32_(ccol, lane);   // lane l holds slot l = jg*8+q
        const int col = (jw * 4 + (lane >> 3)) * 16 + wc2 * 8 + (lane & 7);
        scol[rhalf][col] = cs;
    }
    __syncthreads();
    if (tid < 128) {
        float c = cred[0][tid] + cred[1][tid] + cred[2][tid] + cred[3][tid];
        atomicAdd(&g_c[b * NN + ti * 128 + tid], c);
        if (offd) atomicAdd(&g_c[colbase + tid], scol[0][tid] + scol[1][tid]);
    }
}

// ---------------------------------------------------------------------------
// K5: out[n,m] = g*(p_n*d_m + p_m*d_n) + [n==m]*d_n*d_m.  (unchanged)
// ---------------------------------------------------------------------------
__global__ void __launch_bounds__(256) k5_out(float* __restrict__ out) {
    __shared__ float gsm[64 * 132];        // half-tile, row-major, padded
    __shared__ float dI[128], pI[128], dJ[128], pJ[128];
    TILE_COMMON();

    if (tid < 128) {
        int gi = b * NN + ti * 128 + tid;
        float d = rsq_(fmaf(0.5f, g_c[gi], 1.5f));
        dI[tid] = d; pI[tid] = 0.5f * d / g_s[gi];
        int gj = colbase + tid;
        float d2 = rsq_(fmaf(0.5f, g_c[gj], 1.5f));
        dJ[tid] = d2; pJ[tid] = 0.5f * d2 / g_s[gj];
    }
    float* ob = out + ((size_t)b << 20);
    __syncthreads();

    const float4 dJv = *(const float4*)&dJ[lane * 4];
    const float4 pJv = *(const float4*)&pJ[lane * 4];

    #pragma unroll
    for (int ph = 0; ph < 2; ph++) {
        {
            const float4* gp4 = (const float4*)gtile;
            #pragma unroll
            for (int k = 0; k < 8; k++) {
                const int f = k * 512 + ph * 256 + tid;
                float4 v = gp4[f];
                const int pi = f >> 1, r = f & 1;
                const int j = pi >> 8, w2 = (pi >> 5) & 7, lk = pi & 31;
                const int rl = lk * 2 + r;
                const int col = (w2 & 3) * 4 + j * 16;
                *(float4*)&gsm[rl * 132 + col] = v;
            }
        }
        __syncthreads();

        {
            const int rbase = ph * 64 + w * 8;
            #pragma unroll
            for (int rr = 0; rr < 8; rr++) {
                const int Rl = rbase + rr;
                const float dn = dI[Rl], pn = pI[Rl];
                float4 g4 = *(const float4*)&gsm[(w * 8 + rr) * 132 + lane * 4];
                float4 v;
                v.x = g4.x * fmaf(pn, dJv.x, pJv.x * dn);
                v.y = g4.y * fmaf(pn, dJv.y, pJv.y * dn);
                v.z = g4.z * fmaf(pn, dJv.z, pJv.z * dn);
                v.w = g4.w * fmaf(pn, dJv.w, pJv.w * dn);
                if (!offd && lane == (Rl >> 2)) {
                    const float add = dn * dJ[Rl];
                    if ((rr & 3) == 0) v.x += add;
                    else if ((rr & 3) == 1) v.y += add;
                    else if ((rr & 3) == 2) v.z += add;
                    else v.w += add;
                }
                __stcs((float4*)(ob + (size_t)(ti * 128 + Rl) * NN + tj * 128 + lane * 4), v);
            }
        }

        if (offd) {
            const float dn0 = dI[ph * 64 + lane],      pn0 = pI[ph * 64 + lane];
            const float dn1 = dI[ph * 64 + lane + 32], pn1 = pI[ph * 64 + lane + 32];
            #pragma unroll
            for (int rr = 0; rr < 16; rr++) {
                const int Rm = w * 16 + rr;
                const float dm = dJ[Rm], pm = pJ[Rm];
                const float gA = gsm[lane * 132 + Rm];
                const float gB = gsm[(lane + 32) * 132 + Rm];
                const float vA = gA * fmaf(pm, dn0, pn0 * dm);
                const float vB = gB * fmaf(pm, dn1, pn1 * dm);
                float* mrow = ob + (size_t)(tj * 128 + Rm) * NN + ti * 128 + ph * 64;
                __stcs(mrow + lane, vA);
                __stcs(mrow + lane + 32, vB);
            }
        }
        __syncthreads();
    }
}

// ---------------------------------------------------------------------------
extern "C" void kernel_launch(void* const* d_in, const int* in_sizes, int n_in,
                              void* d_out, int out_size)
{
    const float* xt = (const float*)d_in[0];   // (32, 1024, 64)
    const float* W  = (const float*)d_in[1];   // (64, 24)
    const float* bv = (const float*)d_in[2];   // (24,)
    float* out = (float*)d_out;                // (32, 1024, 1024)

    k1_linrelu<<<512, 256>>>(xt, W, bv);
    k2_gram<<<BB * 36, 128>>>();
    k3_colsum<<<BB * 36, 256>>>();
    k5_out<<<BB * 36, 256>>>(out);
}